// round 9
// baseline (speedup 1.0000x reference)
#include <cuda_runtime.h>
#include <math.h>

#define N_RAYS   262144
#define HIDDEN   256
#define MAX_ITERS 32
#define FAR_DIST 6.0f
#define HIT_T    1e-5f
#define PERT     1e-3f
#define THREADS  256
#define RPT      4
#define NBKT     256
#define NBLK     (N_RAYS / 256)             // 1024 key blocks
#define NWARPS_TOT (N_RAYS / (32 * RPT))    // 2048 trace warps

typedef unsigned long long u64;

// ---- packed f32x2 helpers (sm_103a) ----
__device__ __forceinline__ u64 ffma2(u64 a, u64 b, u64 c) {
    u64 d;
    asm("fma.rn.f32x2 %0, %1, %2, %3;" : "=l"(d) : "l"(a), "l"(b), "l"(c));
    return d;
}
__device__ __forceinline__ u64 pack2(float lo, float hi) {
    u64 r;
    asm("mov.b64 %0, {%1, %2};" : "=l"(r) : "f"(lo), "f"(hi));
    return r;
}
__device__ __forceinline__ float2 unpack2(u64 v) {
    float2 r;
    asm("mov.b64 {%0, %1}, %2;" : "=f"(r.x), "=f"(r.y) : "l"(v));
    return r;
}
__device__ __forceinline__ u64 relu2(u64 h) {
    float2 f = unpack2(h);
    return pack2(fmaxf(f.x, 0.0f), fmaxf(f.y, 0.0f));
}

// ---- sorting scratch (allocation-free: device globals) ----
__device__ int g_bucket[N_RAYS];
__device__ int g_perm[N_RAYS];
__device__ int g_blockhist[NBLK * NBKT];
__device__ int g_blockbase[NBKT * NBLK];
__device__ int g_tot[NBKT];
__device__ int g_bucketbase[NBKT];

__global__ void key_blockhist_kernel(const float* __restrict__ origins,
                                     const float* __restrict__ directions,
                                     const float* __restrict__ center,
                                     const float* __restrict__ radius)
{
    __shared__ int s_hist[NBKT];
    const int t = threadIdx.x;
    s_hist[t] = 0;
    __syncthreads();

    const int r = blockIdx.x * 256 + t;
    const float ox = origins[3 * r + 0] - center[0];
    const float oy = origins[3 * r + 1] - center[1];
    const float oz = origins[3 * r + 2] - center[2];
    const float dx = directions[3 * r + 0];
    const float dy = directions[3 * r + 1];
    const float dz = directions[3 * r + 2];
    const float tca = ox * dx + oy * dy + oz * dz;
    const float oc2 = ox * ox + oy * oy + oz * oz;
    const float b   = sqrtf(fmaxf(oc2 - tca * tca, 0.0f));
    const float key = fabsf(b - radius[0]);
    const float u   = key / (key + 0.05f);
    int bkt = min(127, (int)(u * 128.0f));
    if (b >= radius[0]) bkt += 128;
    g_bucket[r] = bkt;
    atomicAdd(&s_hist[bkt], 1);
    __syncthreads();
    g_blockhist[blockIdx.x * NBKT + t] = s_hist[t];
}

__global__ void bucket_scan_kernel()
{
    __shared__ int s[NBLK];
    const int bucket = blockIdx.x;
    const int t = threadIdx.x;
    const int c = g_blockhist[t * NBKT + bucket];
    s[t] = c;
    __syncthreads();
    #pragma unroll
    for (int off = 1; off < NBLK; off <<= 1) {
        const int v = (t >= off) ? s[t - off] : 0;
        __syncthreads();
        s[t] += v;
        __syncthreads();
    }
    g_blockbase[bucket * NBLK + t] = s[t] - c;
    if (t == NBLK - 1) g_tot[bucket] = s[t];
}

__global__ void total_scan_kernel()
{
    __shared__ int s[NBKT];
    const int t = threadIdx.x;
    const int h = g_tot[t];
    s[t] = h;
    __syncthreads();
    #pragma unroll
    for (int off = 1; off < NBKT; off <<= 1) {
        const int v = (t >= off) ? s[t - off] : 0;
        __syncthreads();
        s[t] += v;
        __syncthreads();
    }
    g_bucketbase[t] = s[t] - h;
}

__global__ void scatter_kernel()
{
    __shared__ int s_base[NBKT];
    __shared__ int s_cnt[NBKT];
    const int t = threadIdx.x;
    s_base[t] = g_bucketbase[t] + g_blockbase[t * NBLK + blockIdx.x];
    s_cnt[t] = 0;
    __syncthreads();
    const int r = blockIdx.x * 256 + t;
    const int bkt = g_bucket[r];
    const int lr = atomicAdd(&s_cnt[bkt], 1);
    g_perm[s_base[bkt] + lr] = r;
}

// ---- main trace kernel: unit-pair packed f32x2 MLP, 4 rays/thread ----
__global__ __launch_bounds__(THREADS, 2)
void sphere_trace_render_kernel(const float* __restrict__ origins,
                                const float* __restrict__ directions,
                                const float* __restrict__ center,
                                const float* __restrict__ radius,
                                const float* __restrict__ W1,
                                const float* __restrict__ b1,
                                const float* __restrict__ W2,
                                const float* __restrict__ b2,
                                const float* __restrict__ Wc1,
                                const float* __restrict__ bc1,
                                const float* __restrict__ Wc2,
                                const float* __restrict__ bc2,
                                float* __restrict__ out)
{
    // Pair-packed weights: pair j = units (2j, 2j+1).
    //   sW1v[2j]   = { (wx_e,wx_o), (wy_e,wy_o) }
    //   sW1v[2j+1] = { (wz_e,wz_o), (b_e, b_o ) }
    __shared__ ulonglong2 sW1v[HIDDEN];
    __shared__ u64        sQv[HIDDEN / 2];     // (q_e, q_o) per pair
    __shared__ ulonglong2 sC1v[HIDDEN];
    __shared__ ulonglong2 sC2xy[HIDDEN / 2];   // { (vx_e,vx_o), (vy_e,vy_o) }
    __shared__ u64        sC2z[HIDDEN / 2];    // (vz_e, vz_o)

    const int t = threadIdx.x;
    {
        const int j = t >> 1;
        float4 v;
        if ((t & 1) == 0)
            v = make_float4(W1[2 * j], W1[2 * j + 1], W1[HIDDEN + 2 * j], W1[HIDDEN + 2 * j + 1]);
        else
            v = make_float4(W1[2 * HIDDEN + 2 * j], W1[2 * HIDDEN + 2 * j + 1], b1[2 * j], b1[2 * j + 1]);
        ((float4*)sW1v)[t] = v;
        if ((t & 1) == 0)
            v = make_float4(Wc1[2 * j], Wc1[2 * j + 1], Wc1[HIDDEN + 2 * j], Wc1[HIDDEN + 2 * j + 1]);
        else
            v = make_float4(Wc1[2 * HIDDEN + 2 * j], Wc1[2 * HIDDEN + 2 * j + 1], bc1[2 * j], bc1[2 * j + 1]);
        ((float4*)sC1v)[t] = v;
    }
    if (t < HIDDEN / 2) {
        ((float2*)sQv)[t] = make_float2(W2[2 * t], W2[2 * t + 1]);
        ((float4*)sC2xy)[t] = make_float4(Wc2[3 * (2 * t)],     Wc2[3 * (2 * t + 1)],
                                          Wc2[3 * (2 * t) + 1], Wc2[3 * (2 * t + 1) + 1]);
        ((float2*)sC2z)[t]  = make_float2(Wc2[3 * (2 * t) + 2], Wc2[3 * (2 * t + 1) + 2]);
    }
    __syncthreads();

    // Warp -> sorted segment, hard/easy folded for SM load balance.
    const int w = t >> 5, lane = t & 31;
    const int g = blockIdx.x * (THREADS / 32) + w;                     // 0..2047
    const int s = (g & 1) ? (NWARPS_TOT - 1 - (g >> 1)) : (g >> 1);
    const int base = s * (32 * RPT) + lane;

    int ray[RPT];
    float px[RPT], py[RPT], pz[RPT], dx[RPT], dy[RPT], dz[RPT], dist[RPT];
    bool unf[RPT], hit[RPT];
    #pragma unroll
    for (int r = 0; r < RPT; ++r) {
        ray[r] = g_perm[base + 32 * r];
        px[r] = origins[3 * ray[r] + 0];
        py[r] = origins[3 * ray[r] + 1];
        pz[r] = origins[3 * ray[r] + 2];
        dx[r] = directions[3 * ray[r] + 0];
        dy[r] = directions[3 * ray[r] + 1];
        dz[r] = directions[3 * ray[r] + 2];
        dist[r] = 0.0f;
        unf[r] = true;
        hit[r] = false;
    }

    const float cx  = center[0];
    const float cy  = center[1];
    const float cz  = center[2];
    const float rad = radius[0];
    const float bb2 = b2[0];
    const float bo0 = bc2[0];
    const float bo1 = bc2[1];
    const float bo2 = bc2[2];

    for (int it = 0; it < MAX_ITERS; ++it) {
        const bool alldone = !unf[0] && !unf[1] && !unf[2] && !unf[3];
        if (__all_sync(0xFFFFFFFFu, alldone)) break;

        // ---- Geometry (FROZEN form): norm = fma(rz,rz, fma(rx,rx, ry*ry))
        float base_[RPT];
        #pragma unroll
        for (int r = 0; r < RPT; ++r) {
            const float rx = px[r] - cx, ry = py[r] - cy, rz = pz[r] - cz;
            base_[r] = sqrtf(fmaf(rz, rz, fmaf(rx, rx, __fmul_rn(ry, ry)))) - rad;
        }

        // ---- Packed perturbation MLP: 2 hidden units per FFMA2, 4 rays.
        u64 pxx[RPT], pyy[RPT], pzz[RPT], acc[RPT];
        #pragma unroll
        for (int r = 0; r < RPT; ++r) {
            pxx[r] = pack2(px[r], px[r]);
            pyy[r] = pack2(py[r], py[r]);
            pzz[r] = pack2(pz[r], pz[r]);
            acc[r] = 0ULL;                      // (0.0f, 0.0f)
        }
        #pragma unroll 8
        for (int j = 0; j < HIDDEN / 2; ++j) {
            const ulonglong2 wxy = sW1v[2 * j];
            const ulonglong2 wzb = sW1v[2 * j + 1];
            const u64 qq = sQv[j];
            #pragma unroll
            for (int r = 0; r < RPT; ++r) {
                const u64 h = ffma2(wxy.x, pxx[r],
                              ffma2(wxy.y, pyy[r],
                              ffma2(wzb.x, pzz[r], wzb.y)));
                acc[r] = ffma2(relu2(h), qq, acc[r]);
            }
        }

        // ---- d + exact reference mask semantics (FROZEN).
        #pragma unroll
        for (int r = 0; r < RPT; ++r) {
            const float2 af = unpack2(acc[r]);
            const float d = base_[r] + PERT * tanhf((af.x + af.y) + bb2);
            const bool curr_hit = fabsf(d) < HIT_T;
            const bool missed   = dist[r] > FAR_DIST;
            hit[r] = hit[r] || (unf[r] && curr_hit);
            const bool still = unf[r] && !curr_hit && !missed;
            if (still) {
                px[r] = fmaf(d, dx[r], px[r]);
                py[r] = fmaf(d, dy[r], py[r]);
                pz[r] = fmaf(d, dz[r], pz[r]);
                dist[r] += d;
            }
            unf[r] = still;
        }
    }

    // ---- Color MLP (packed, warp-coherent post-sort).
    float outc[RPT][3];
    #pragma unroll
    for (int r = 0; r < RPT; ++r)
        outc[r][0] = outc[r][1] = outc[r][2] = 0.0f;

    if (hit[0] || hit[1] || hit[2] || hit[3]) {
        u64 pxx[RPT], pyy[RPT], pzz[RPT];
        u64 c0[RPT], c1[RPT], c2[RPT];
        #pragma unroll
        for (int r = 0; r < RPT; ++r) {
            pxx[r] = pack2(px[r], px[r]);
            pyy[r] = pack2(py[r], py[r]);
            pzz[r] = pack2(pz[r], pz[r]);
            c0[r] = c1[r] = c2[r] = 0ULL;
        }
        #pragma unroll 4
        for (int j = 0; j < HIDDEN / 2; ++j) {
            const ulonglong2 wxy = sC1v[2 * j];
            const ulonglong2 wzb = sC1v[2 * j + 1];
            const ulonglong2 vxy = sC2xy[j];
            const u64 vz = sC2z[j];
            #pragma unroll
            for (int r = 0; r < RPT; ++r) {
                const u64 h = relu2(ffma2(wxy.x, pxx[r],
                                   ffma2(wxy.y, pyy[r],
                                   ffma2(wzb.x, pzz[r], wzb.y))));
                c0[r] = ffma2(h, vxy.x, c0[r]);
                c1[r] = ffma2(h, vxy.y, c1[r]);
                c2[r] = ffma2(h, vz,    c2[r]);
            }
        }
        #pragma unroll
        for (int r = 0; r < RPT; ++r) {
            if (hit[r]) {
                const float2 f0 = unpack2(c0[r]);
                const float2 f1 = unpack2(c1[r]);
                const float2 f2 = unpack2(c2[r]);
                outc[r][0] = 1.0f / (1.0f + __expf(-((f0.x + f0.y) + bo0)));
                outc[r][1] = 1.0f / (1.0f + __expf(-((f1.x + f1.y) + bo1)));
                outc[r][2] = 1.0f / (1.0f + __expf(-((f2.x + f2.y) + bo2)));
            }
        }
    }
    #pragma unroll
    for (int r = 0; r < RPT; ++r) {
        out[3 * ray[r] + 0] = outc[r][0];
        out[3 * ray[r] + 1] = outc[r][1];
        out[3 * ray[r] + 2] = outc[r][2];
    }
}

extern "C" void kernel_launch(void* const* d_in, const int* in_sizes, int n_in,
                              void* d_out, int out_size)
{
    const float* origins    = (const float*)d_in[0];
    const float* directions = (const float*)d_in[1];
    const float* center     = (const float*)d_in[2];
    const float* radius     = (const float*)d_in[3];
    const float* W1         = (const float*)d_in[4];
    const float* b1         = (const float*)d_in[5];
    const float* W2         = (const float*)d_in[6];
    const float* b2         = (const float*)d_in[7];
    const float* Wc1        = (const float*)d_in[8];
    const float* bc1        = (const float*)d_in[9];
    const float* Wc2        = (const float*)d_in[10];
    const float* bc2        = (const float*)d_in[11];
    float* out = (float*)d_out;

    // Counting sort by difficulty — zero global atomics, graph-capturable.
    key_blockhist_kernel<<<NBLK, 256>>>(origins, directions, center, radius);
    bucket_scan_kernel<<<NBKT, NBLK>>>();
    total_scan_kernel<<<1, NBKT>>>();
    scatter_kernel<<<NBLK, 256>>>();

    const int blocks = N_RAYS / (THREADS * RPT);  // 256
    sphere_trace_render_kernel<<<blocks, THREADS>>>(
        origins, directions, center, radius,
        W1, b1, W2, b2, Wc1, bc1, Wc2, bc2, out);
}

// round 10
// speedup vs baseline: 1.3504x; 1.3504x over previous
#include <cuda_runtime.h>
#include <math.h>

#define N_RAYS   262144
#define HIDDEN   256
#define MAX_ITERS 32
#define FAR_DIST 6.0f
#define HIT_T    1e-5f
#define PERT     1e-3f
#define THREADS  256
#define RPT      2
#define NBKT     256
#define NBLK     (N_RAYS / 256)             // 1024 key blocks
#define NWARPS_TOT (N_RAYS / (32 * RPT))    // 4096 trace warps

typedef unsigned long long u64;

// ---- packed f32x2 helpers (sm_103a) ----
__device__ __forceinline__ u64 ffma2(u64 a, u64 b, u64 c) {
    u64 d;
    asm("fma.rn.f32x2 %0, %1, %2, %3;" : "=l"(d) : "l"(a), "l"(b), "l"(c));
    return d;
}
__device__ __forceinline__ u64 pack2(float lo, float hi) {
    u64 r;
    asm("mov.b64 %0, {%1, %2};" : "=l"(r) : "f"(lo), "f"(hi));
    return r;
}
__device__ __forceinline__ float2 unpack2(u64 v) {
    float2 r;
    asm("mov.b64 {%0, %1}, %2;" : "=f"(r.x), "=f"(r.y) : "l"(v));
    return r;
}
__device__ __forceinline__ u64 relu2(u64 h) {
    float2 f = unpack2(h);
    return pack2(fmaxf(f.x, 0.0f), fmaxf(f.y, 0.0f));
}

// ---- sorting scratch (allocation-free: device globals) ----
__device__ int g_bucket[N_RAYS];
__device__ int g_perm[N_RAYS];
__device__ int g_blockhist[NBLK * NBKT];
__device__ int g_blockbase[NBKT * NBLK];
__device__ int g_tot[NBKT];
__device__ int g_bucketbase[NBKT];

__global__ void key_blockhist_kernel(const float* __restrict__ origins,
                                     const float* __restrict__ directions,
                                     const float* __restrict__ center,
                                     const float* __restrict__ radius)
{
    __shared__ int s_hist[NBKT];
    const int t = threadIdx.x;
    s_hist[t] = 0;
    __syncthreads();

    const int r = blockIdx.x * 256 + t;
    const float ox = origins[3 * r + 0] - center[0];
    const float oy = origins[3 * r + 1] - center[1];
    const float oz = origins[3 * r + 2] - center[2];
    const float dx = directions[3 * r + 0];
    const float dy = directions[3 * r + 1];
    const float dz = directions[3 * r + 2];
    const float tca = ox * dx + oy * dy + oz * dz;
    const float oc2 = ox * ox + oy * oy + oz * oz;
    const float b   = sqrtf(fmaxf(oc2 - tca * tca, 0.0f));
    const float key = fabsf(b - radius[0]);
    const float u   = key / (key + 0.05f);
    int bkt = min(127, (int)(u * 128.0f));
    if (b >= radius[0]) bkt += 128;
    g_bucket[r] = bkt;
    atomicAdd(&s_hist[bkt], 1);
    __syncthreads();
    g_blockhist[blockIdx.x * NBKT + t] = s_hist[t];
}

__global__ void bucket_scan_kernel()
{
    __shared__ int s[NBLK];
    const int bucket = blockIdx.x;
    const int t = threadIdx.x;
    const int c = g_blockhist[t * NBKT + bucket];
    s[t] = c;
    __syncthreads();
    #pragma unroll
    for (int off = 1; off < NBLK; off <<= 1) {
        const int v = (t >= off) ? s[t - off] : 0;
        __syncthreads();
        s[t] += v;
        __syncthreads();
    }
    g_blockbase[bucket * NBLK + t] = s[t] - c;
    if (t == NBLK - 1) g_tot[bucket] = s[t];
}

__global__ void total_scan_kernel()
{
    __shared__ int s[NBKT];
    const int t = threadIdx.x;
    const int h = g_tot[t];
    s[t] = h;
    __syncthreads();
    #pragma unroll
    for (int off = 1; off < NBKT; off <<= 1) {
        const int v = (t >= off) ? s[t - off] : 0;
        __syncthreads();
        s[t] += v;
        __syncthreads();
    }
    g_bucketbase[t] = s[t] - h;
}

__global__ void scatter_kernel()
{
    __shared__ int s_base[NBKT];
    __shared__ int s_cnt[NBKT];
    const int t = threadIdx.x;
    s_base[t] = g_bucketbase[t] + g_blockbase[t * NBLK + blockIdx.x];
    s_cnt[t] = 0;
    __syncthreads();
    const int r = blockIdx.x * 256 + t;
    const int bkt = g_bucket[r];
    const int lr = atomicAdd(&s_cnt[bkt], 1);
    g_perm[s_base[bkt] + lr] = r;
}

// ---- main trace kernel: unit-pair packed f32x2 MLP, 2 rays/thread ----
__global__ __launch_bounds__(THREADS)
void sphere_trace_render_kernel(const float* __restrict__ origins,
                                const float* __restrict__ directions,
                                const float* __restrict__ center,
                                const float* __restrict__ radius,
                                const float* __restrict__ W1,
                                const float* __restrict__ b1,
                                const float* __restrict__ W2,
                                const float* __restrict__ b2,
                                const float* __restrict__ Wc1,
                                const float* __restrict__ bc1,
                                const float* __restrict__ Wc2,
                                const float* __restrict__ bc2,
                                float* __restrict__ out)
{
    // Pair-packed weights: pair j = units (2j, 2j+1).
    __shared__ ulonglong2 sW1v[HIDDEN];        // [2j]={(wx_e,wx_o),(wy_e,wy_o)} [2j+1]={(wz_e,wz_o),(b_e,b_o)}
    __shared__ u64        sQv[HIDDEN / 2];     // (q_e, q_o) per pair
    __shared__ ulonglong2 sC1v[HIDDEN];
    __shared__ ulonglong2 sC2xy[HIDDEN / 2];   // { (vx_e,vx_o), (vy_e,vy_o) }
    __shared__ u64        sC2z[HIDDEN / 2];    // (vz_e, vz_o)

    const int t = threadIdx.x;
    {
        const int j = t >> 1;
        float4 v;
        if ((t & 1) == 0)
            v = make_float4(W1[2 * j], W1[2 * j + 1], W1[HIDDEN + 2 * j], W1[HIDDEN + 2 * j + 1]);
        else
            v = make_float4(W1[2 * HIDDEN + 2 * j], W1[2 * HIDDEN + 2 * j + 1], b1[2 * j], b1[2 * j + 1]);
        ((float4*)sW1v)[t] = v;
        if ((t & 1) == 0)
            v = make_float4(Wc1[2 * j], Wc1[2 * j + 1], Wc1[HIDDEN + 2 * j], Wc1[HIDDEN + 2 * j + 1]);
        else
            v = make_float4(Wc1[2 * HIDDEN + 2 * j], Wc1[2 * HIDDEN + 2 * j + 1], bc1[2 * j], bc1[2 * j + 1]);
        ((float4*)sC1v)[t] = v;
    }
    if (t < HIDDEN / 2) {
        ((float2*)sQv)[t] = make_float2(W2[2 * t], W2[2 * t + 1]);
        ((float4*)sC2xy)[t] = make_float4(Wc2[3 * (2 * t)],     Wc2[3 * (2 * t + 1)],
                                          Wc2[3 * (2 * t) + 1], Wc2[3 * (2 * t + 1) + 1]);
        ((float2*)sC2z)[t]  = make_float2(Wc2[3 * (2 * t) + 2], Wc2[3 * (2 * t + 1) + 2]);
    }
    __syncthreads();

    // Warp -> sorted segment, hard/easy folded for SM load balance.
    const int w = t >> 5, lane = t & 31;
    const int g = blockIdx.x * (THREADS / 32) + w;                     // 0..4095
    const int s = (g & 1) ? (NWARPS_TOT - 1 - (g >> 1)) : (g >> 1);
    const int base = s * (32 * RPT) + lane;

    const int rayA = g_perm[base];
    const int rayB = g_perm[base + 32];

    float pxA = origins[3 * rayA + 0], pyA = origins[3 * rayA + 1], pzA = origins[3 * rayA + 2];
    float pxB = origins[3 * rayB + 0], pyB = origins[3 * rayB + 1], pzB = origins[3 * rayB + 2];
    const float dxA = directions[3 * rayA + 0], dyA = directions[3 * rayA + 1], dzA = directions[3 * rayA + 2];
    const float dxB = directions[3 * rayB + 0], dyB = directions[3 * rayB + 1], dzB = directions[3 * rayB + 2];

    const float cx  = center[0];
    const float cy  = center[1];
    const float cz  = center[2];
    const float rad = radius[0];
    const float bb2 = b2[0];
    const float bo0 = bc2[0];
    const float bo1 = bc2[1];
    const float bo2 = bc2[2];

    float distA = 0.0f, distB = 0.0f;
    bool  unfA = true, unfB = true;
    bool  hitA = false, hitB = false;

    for (int it = 0; it < MAX_ITERS; ++it) {
        if (__all_sync(0xFFFFFFFFu, !unfA && !unfB)) break;

        // ---- Geometry (FROZEN form): norm = fma(rz,rz, fma(rx,rx, ry*ry))
        const float rxA = pxA - cx, ryA = pyA - cy, rzA = pzA - cz;
        const float baseA = sqrtf(fmaf(rzA, rzA, fmaf(rxA, rxA, __fmul_rn(ryA, ryA)))) - rad;
        const float rxB = pxB - cx, ryB = pyB - cy, rzB = pzB - cz;
        const float baseB = sqrtf(fmaf(rzB, rzB, fmaf(rxB, rxB, __fmul_rn(ryB, ryB)))) - rad;

        // ---- Packed perturbation MLP: 2 hidden units per FFMA2, 2 rays.
        const u64 pxxA = pack2(pxA, pxA), pyyA = pack2(pyA, pyA), pzzA = pack2(pzA, pzA);
        const u64 pxxB = pack2(pxB, pxB), pyyB = pack2(pyB, pyB), pzzB = pack2(pzB, pzB);
        u64 accA = 0ULL, accB = 0ULL;
        #pragma unroll 8
        for (int j = 0; j < HIDDEN / 2; ++j) {
            const ulonglong2 wxy = sW1v[2 * j];
            const ulonglong2 wzb = sW1v[2 * j + 1];
            const u64 qq = sQv[j];
            const u64 hA = ffma2(wxy.x, pxxA, ffma2(wxy.y, pyyA, ffma2(wzb.x, pzzA, wzb.y)));
            const u64 hB = ffma2(wxy.x, pxxB, ffma2(wxy.y, pyyB, ffma2(wzb.x, pzzB, wzb.y)));
            accA = ffma2(relu2(hA), qq, accA);
            accB = ffma2(relu2(hB), qq, accB);
        }
        const float2 afA = unpack2(accA);
        const float2 afB = unpack2(accB);
        const float dA = baseA + PERT * tanhf((afA.x + afA.y) + bb2);
        const float dB = baseB + PERT * tanhf((afB.x + afB.y) + bb2);

        // ---- Exact reference mask semantics (FROZEN).
        {
            const bool curr_hit = fabsf(dA) < HIT_T;
            const bool missed   = distA > FAR_DIST;
            hitA = hitA || (unfA && curr_hit);
            const bool still = unfA && !curr_hit && !missed;
            if (still) {
                pxA = fmaf(dA, dxA, pxA);
                pyA = fmaf(dA, dyA, pyA);
                pzA = fmaf(dA, dzA, pzA);
                distA += dA;
            }
            unfA = still;
        }
        {
            const bool curr_hit = fabsf(dB) < HIT_T;
            const bool missed   = distB > FAR_DIST;
            hitB = hitB || (unfB && curr_hit);
            const bool still = unfB && !curr_hit && !missed;
            if (still) {
                pxB = fmaf(dB, dxB, pxB);
                pyB = fmaf(dB, dyB, pyB);
                pzB = fmaf(dB, dzB, pzB);
                distB += dB;
            }
            unfB = still;
        }
    }

    // ---- Color MLP (packed, warp-coherent post-sort).
    float rA = 0.0f, gA = 0.0f, bA = 0.0f;
    float rB = 0.0f, gB = 0.0f, bB = 0.0f;
    if (hitA || hitB) {
        const u64 pxxA = pack2(pxA, pxA), pyyA = pack2(pyA, pyA), pzzA = pack2(pzA, pzA);
        const u64 pxxB = pack2(pxB, pxB), pyyB = pack2(pyB, pyB), pzzB = pack2(pzB, pzB);
        u64 c0A = 0ULL, c1A = 0ULL, c2A = 0ULL;
        u64 c0B = 0ULL, c1B = 0ULL, c2B = 0ULL;
        #pragma unroll 4
        for (int j = 0; j < HIDDEN / 2; ++j) {
            const ulonglong2 wxy = sC1v[2 * j];
            const ulonglong2 wzb = sC1v[2 * j + 1];
            const ulonglong2 vxy = sC2xy[j];
            const u64 vz = sC2z[j];
            const u64 hA = relu2(ffma2(wxy.x, pxxA, ffma2(wxy.y, pyyA, ffma2(wzb.x, pzzA, wzb.y))));
            const u64 hB = relu2(ffma2(wxy.x, pxxB, ffma2(wxy.y, pyyB, ffma2(wzb.x, pzzB, wzb.y))));
            c0A = ffma2(hA, vxy.x, c0A);  c0B = ffma2(hB, vxy.x, c0B);
            c1A = ffma2(hA, vxy.y, c1A);  c1B = ffma2(hB, vxy.y, c1B);
            c2A = ffma2(hA, vz,    c2A);  c2B = ffma2(hB, vz,    c2B);
        }
        if (hitA) {
            const float2 f0 = unpack2(c0A), f1 = unpack2(c1A), f2 = unpack2(c2A);
            rA = 1.0f / (1.0f + __expf(-((f0.x + f0.y) + bo0)));
            gA = 1.0f / (1.0f + __expf(-((f1.x + f1.y) + bo1)));
            bA = 1.0f / (1.0f + __expf(-((f2.x + f2.y) + bo2)));
        }
        if (hitB) {
            const float2 f0 = unpack2(c0B), f1 = unpack2(c1B), f2 = unpack2(c2B);
            rB = 1.0f / (1.0f + __expf(-((f0.x + f0.y) + bo0)));
            gB = 1.0f / (1.0f + __expf(-((f1.x + f1.y) + bo1)));
            bB = 1.0f / (1.0f + __expf(-((f2.x + f2.y) + bo2)));
        }
    }
    out[3 * rayA + 0] = rA;
    out[3 * rayA + 1] = gA;
    out[3 * rayA + 2] = bA;
    out[3 * rayB + 0] = rB;
    out[3 * rayB + 1] = gB;
    out[3 * rayB + 2] = bB;
}

extern "C" void kernel_launch(void* const* d_in, const int* in_sizes, int n_in,
                              void* d_out, int out_size)
{
    const float* origins    = (const float*)d_in[0];
    const float* directions = (const float*)d_in[1];
    const float* center     = (const float*)d_in[2];
    const float* radius     = (const float*)d_in[3];
    const float* W1         = (const float*)d_in[4];
    const float* b1         = (const float*)d_in[5];
    const float* W2         = (const float*)d_in[6];
    const float* b2         = (const float*)d_in[7];
    const float* Wc1        = (const float*)d_in[8];
    const float* bc1        = (const float*)d_in[9];
    const float* Wc2        = (const float*)d_in[10];
    const float* bc2        = (const float*)d_in[11];
    float* out = (float*)d_out;

    // Counting sort by difficulty — zero global atomics, graph-capturable.
    key_blockhist_kernel<<<NBLK, 256>>>(origins, directions, center, radius);
    bucket_scan_kernel<<<NBKT, NBLK>>>();
    total_scan_kernel<<<1, NBKT>>>();
    scatter_kernel<<<NBLK, 256>>>();

    const int blocks = N_RAYS / (THREADS * RPT);  // 512
    sphere_trace_render_kernel<<<blocks, THREADS>>>(
        origins, directions, center, radius,
        W1, b1, W2, b2, Wc1, bc1, Wc2, bc2, out);
}